// round 8
// baseline (speedup 1.0000x reference)
#include <cuda_runtime.h>

#define BS   256
#define FTN  8
#define ATN  264   // BS + FTN
#define NDIM 512

#define NBLOCKS    8448          // (BS*ATN warps * 32) / 256
#define TAIL       64            // blocks that do lse work (8 warps * 8 terms... 1 term/warp)
#define TERMS      (2 * BS)      // 512 CE terms

// Scratch (no allocations allowed)
__device__ float g_logits[BS * ATN];
__device__ float g_logitsT[BS * BS];   // g_logitsT[a*BS + b] = logits[b, a], a < 256
__device__ int   g_count  = 0;         // dot-completion tickets
__device__ int   g_done2  = 0;         // tail-completion tickets (for reset)

__device__ __forceinline__ void acc3(const float4& x, const float4& t,
                                     float& dot, float& in2, float& tn2)
{
    dot += x.x * t.x + x.y * t.y + x.z * t.z + x.w * t.w;
    in2 += x.x * x.x + x.y * x.y + x.z * x.z + x.w * x.w;
    tn2 += t.x * t.x + t.y * t.y + t.z * t.z + t.w * t.w;
}

// ---------------------------------------------------------------------------
// Single fused kernel.
// Phase 1 (all 8448 blocks): one warp per (b,a): logit = s * dot / (|i||t|),
//   8 front-batched LDG.128, evict-first image stream. Stores row-major +
//   transposed square block.
// Phase 2 (last 64 blocks to finish): spin on g_count, then each warp computes
//   one lse(row) - diag CE term from L2-hot logits; 1 atomicAdd per block.
// ---------------------------------------------------------------------------
__global__ __launch_bounds__(256) void cl_fused_kernel(
    const float* __restrict__ img,
    const float* __restrict__ rand_t,
    const float* __restrict__ false_t,
    const float* __restrict__ logit_scale,
    float* __restrict__ out)
{
    __shared__ int   s_ticket;
    __shared__ float s_term[8];

    int wid   = threadIdx.x >> 5;
    int lane  = threadIdx.x & 31;
    int gwarp = blockIdx.x * 8 + wid;
    if (blockIdx.x == 0 && threadIdx.x == 0) out[0] = 0.0f;

    // ---------------- Phase 1: dot products ----------------
    {
        int b = gwarp / ATN;
        int a = gwarp - b * ATN;

        const float4* ip = (const float4*)(img + (size_t)gwarp * NDIM);
        const float*  tbase = (a < BS)
            ? (rand_t + (size_t)a * NDIM)
            : (false_t + ((size_t)b * FTN + (a - BS)) * NDIM);
        const float4* tp = (const float4*)tbase;

        float4 x0 = __ldcs(ip + lane);
        float4 x1 = __ldcs(ip + lane + 32);
        float4 x2 = __ldcs(ip + lane + 64);
        float4 x3 = __ldcs(ip + lane + 96);
        float4 t0 = __ldg(tp + lane);
        float4 t1 = __ldg(tp + lane + 32);
        float4 t2 = __ldg(tp + lane + 64);
        float4 t3 = __ldg(tp + lane + 96);

        float dot = 0.f, in2 = 0.f, tn2 = 0.f;
        acc3(x0, t0, dot, in2, tn2);
        acc3(x1, t1, dot, in2, tn2);
        acc3(x2, t2, dot, in2, tn2);
        acc3(x3, t3, dot, in2, tn2);

        #pragma unroll
        for (int o = 16; o > 0; o >>= 1) {
            dot += __shfl_xor_sync(0xffffffffu, dot, o);
            in2 += __shfl_xor_sync(0xffffffffu, in2, o);
            tn2 += __shfl_xor_sync(0xffffffffu, tn2, o);
        }
        if (lane == 0) {
            float scale = expf(logit_scale[0]);
            float lg = scale * dot * rsqrtf(in2 * tn2);
            g_logits[gwarp] = lg;
            if (a < BS) g_logitsT[(size_t)a * BS + b] = lg;
        }
    }

    // ---------------- Ticket: publish writes, take completion ticket --------
    __syncthreads();
    __threadfence();
    if (threadIdx.x == 0)
        s_ticket = atomicAdd(&g_count, 1);
    __syncthreads();
    int ticket = s_ticket;

    if (ticket < NBLOCKS - TAIL) return;

    // ---------------- Phase 2: lse tail (last 64 blocks) --------------------
    if (threadIdx.x == 0) {
        while (*(volatile int*)&g_count < NBLOCKS) { }
    }
    __syncthreads();
    __threadfence();

    // term index: one per warp.  terms 0..255 = image rows, 256..511 = text cols
    int term = (ticket - (NBLOCKS - TAIL)) * 8 + wid;

    float v[9];
    float diag;
    if (term < BS) {
        const float* row = g_logits + (size_t)term * ATN;
        #pragma unroll
        for (int i = 0; i < 8; i++) v[i] = row[lane + 32 * i];
        v[8] = (lane < FTN) ? row[BS + lane] : -1e30f;
        diag = row[term];
    } else {
        int a = term - BS;
        const float* row = g_logitsT + (size_t)a * BS;
        #pragma unroll
        for (int i = 0; i < 8; i++) v[i] = row[lane + 32 * i];
        v[8] = -1e30f;
        diag = row[a];
    }

    float m = v[0];
    #pragma unroll
    for (int i = 1; i < 9; i++) m = fmaxf(m, v[i]);
    #pragma unroll
    for (int o = 16; o > 0; o >>= 1)
        m = fmaxf(m, __shfl_xor_sync(0xffffffffu, m, o));

    float s = 0.f;
    #pragma unroll
    for (int i = 0; i < 9; i++) s += expf(v[i] - m);   // exp(-1e30 - m) == 0
    #pragma unroll
    for (int o = 16; o > 0; o >>= 1)
        s += __shfl_xor_sync(0xffffffffu, s, o);

    if (lane == 0)
        s_term[wid] = m + logf(s) - diag;
    __syncthreads();

    if (wid == 0) {
        float t = (lane < 8) ? s_term[lane] : 0.f;
        #pragma unroll
        for (int o = 4; o > 0; o >>= 1)
            t += __shfl_xor_sync(0xffffffffu, t, o);
        if (lane == 0) {
            atomicAdd(out, t * (1.0f / (2.0f * BS)));
            // last tail block resets counters for the next graph replay
            __threadfence();
            if (atomicAdd(&g_done2, 1) == TAIL - 1) {
                g_count = 0;
                g_done2 = 0;
            }
        }
    }
}

extern "C" void kernel_launch(void* const* d_in, const int* in_sizes, int n_in,
                              void* d_out, int out_size)
{
    const float* img     = (const float*)d_in[0];  // [256, 264, 512]
    const float* rand_t  = (const float*)d_in[1];  // [256, 512]
    const float* false_t = (const float*)d_in[2];  // [2048, 512]
    const float* lscale  = (const float*)d_in[3];  // [1]
    float* out = (float*)d_out;

    cl_fused_kernel<<<NBLOCKS, 256>>>(img, rand_t, false_t, lscale, out);
}

// round 10
// speedup vs baseline: 1.2684x; 1.2684x over previous
#include <cuda_runtime.h>

#define BS   256
#define FTN  8
#define ATN  264   // BS + FTN
#define NDIM 512

// Scratch (no allocations allowed): logits [256 x 264] + transposed square part
__device__ float g_logits[BS * ATN];
__device__ float g_logitsT[BS * BS];   // g_logitsT[a*BS + b] = logits[b, a], a < 256

// Ordered (volatile) vector loads: guarantees all 8 LDG.128 issue before use.
__device__ __forceinline__ float4 ldcs4(const float4* p) {
    float4 v;
    asm volatile("ld.global.cs.v4.f32 {%0,%1,%2,%3}, [%4];"
                 : "=f"(v.x), "=f"(v.y), "=f"(v.z), "=f"(v.w) : "l"(p));
    return v;
}
__device__ __forceinline__ float4 ldnc4(const float4* p) {
    float4 v;
    asm volatile("ld.global.nc.v4.f32 {%0,%1,%2,%3}, [%4];"
                 : "=f"(v.x), "=f"(v.y), "=f"(v.z), "=f"(v.w) : "l"(p));
    return v;
}

__device__ __forceinline__ void acc3(const float4& x, const float4& t,
                                     float& dot, float& in2, float& tn2)
{
    dot += x.x * t.x + x.y * t.y + x.z * t.z + x.w * t.w;
    in2 += x.x * x.x + x.y * x.y + x.z * x.z + x.w * x.w;
    tn2 += t.x * t.x + t.y * t.y + t.z * t.z + t.w * t.w;
}

// ---------------------------------------------------------------------------
// Kernel 1: one warp per (b, a). 8 LDG.128 force-batched via asm volatile
// (hardware MLP=8). Image stream evict-first; text stream read-only cached.
// ---------------------------------------------------------------------------
__global__ __launch_bounds__(256) void cl_dot_kernel(
    const float* __restrict__ img,
    const float* __restrict__ rand_t,
    const float* __restrict__ false_t,
    const float* __restrict__ logit_scale,
    float* __restrict__ out)
{
    int gwarp = (blockIdx.x * blockDim.x + threadIdx.x) >> 5;
    int lane  = threadIdx.x & 31;
    if (blockIdx.x == 0 && threadIdx.x == 0) out[0] = 0.0f;
    if (gwarp >= BS * ATN) return;

    int b = gwarp / ATN;
    int a = gwarp - b * ATN;

    const float4* ip = (const float4*)(img + (size_t)gwarp * NDIM);
    const float*  tbase = (a < BS)
        ? (rand_t + (size_t)a * NDIM)
        : (false_t + ((size_t)b * FTN + (a - BS)) * NDIM);
    const float4* tp = (const float4*)tbase;

    // All 8 loads issued back-to-back (volatile asm is order-preserving).
    float4 x0 = ldcs4(ip + lane);
    float4 x1 = ldcs4(ip + lane + 32);
    float4 x2 = ldcs4(ip + lane + 64);
    float4 x3 = ldcs4(ip + lane + 96);
    float4 t0 = ldnc4(tp + lane);
    float4 t1 = ldnc4(tp + lane + 32);
    float4 t2 = ldnc4(tp + lane + 64);
    float4 t3 = ldnc4(tp + lane + 96);

    float dot = 0.f, in2 = 0.f, tn2 = 0.f;
    acc3(x0, t0, dot, in2, tn2);
    acc3(x1, t1, dot, in2, tn2);
    acc3(x2, t2, dot, in2, tn2);
    acc3(x3, t3, dot, in2, tn2);

    #pragma unroll
    for (int o = 16; o > 0; o >>= 1) {
        dot += __shfl_xor_sync(0xffffffffu, dot, o);
        in2 += __shfl_xor_sync(0xffffffffu, in2, o);
        tn2 += __shfl_xor_sync(0xffffffffu, tn2, o);
    }
    if (lane == 0) {
        float scale = expf(logit_scale[0]);
        float lg = scale * dot * rsqrtf(in2 * tn2);
        g_logits[gwarp] = lg;
        if (a < BS) g_logitsT[(size_t)a * BS + b] = lg;
    }
}

// ---------------------------------------------------------------------------
// Kernel 2 (R7 form): one warp per CE term, coalesced, one atomic per block.
// ---------------------------------------------------------------------------
__global__ __launch_bounds__(256) void cl_lse_kernel(float* __restrict__ out)
{
    __shared__ float s_term[8];
    int gw   = (blockIdx.x * blockDim.x + threadIdx.x) >> 5;
    int wid  = threadIdx.x >> 5;
    int lane = threadIdx.x & 31;

    float v[9];
    float diag;
    if (gw < BS) {
        const float* row = g_logits + (size_t)gw * ATN;
        #pragma unroll
        for (int i = 0; i < 8; i++) v[i] = row[lane + 32 * i];
        v[8] = (lane < FTN) ? row[BS + lane] : -1e30f;
        diag = row[gw];
    } else {
        int a = gw - BS;
        const float* row = g_logitsT + (size_t)a * BS;
        #pragma unroll
        for (int i = 0; i < 8; i++) v[i] = row[lane + 32 * i];
        v[8] = -1e30f;
        diag = row[a];
    }

    float m = v[0];
    #pragma unroll
    for (int i = 1; i < 9; i++) m = fmaxf(m, v[i]);
    #pragma unroll
    for (int o = 16; o > 0; o >>= 1)
        m = fmaxf(m, __shfl_xor_sync(0xffffffffu, m, o));

    float s = 0.f;
    #pragma unroll
    for (int i = 0; i < 9; i++) s += expf(v[i] - m);   // exp(-1e30 - m) == 0
    #pragma unroll
    for (int o = 16; o > 0; o >>= 1)
        s += __shfl_xor_sync(0xffffffffu, s, o);

    if (lane == 0)
        s_term[wid] = m + logf(s) - diag;
    __syncthreads();

    if (wid == 0) {
        float t = (lane < 8) ? s_term[lane] : 0.f;
        #pragma unroll
        for (int o = 4; o > 0; o >>= 1)
            t += __shfl_xor_sync(0xffffffffu, t, o);
        if (lane == 0)
            atomicAdd(out, t * (1.0f / (2.0f * BS)));
    }
}

extern "C" void kernel_launch(void* const* d_in, const int* in_sizes, int n_in,
                              void* d_out, int out_size)
{
    const float* img     = (const float*)d_in[0];  // [256, 264, 512]
    const float* rand_t  = (const float*)d_in[1];  // [256, 512]
    const float* false_t = (const float*)d_in[2];  // [2048, 512]
    const float* lscale  = (const float*)d_in[3];  // [1]
    float* out = (float*)d_out;

    const int nwarps1 = BS * ATN;                   // 67584
    const int tpb = 256;
    const int nblocks1 = (nwarps1 * 32 + tpb - 1) / tpb;  // 8448

    cl_dot_kernel<<<nblocks1, tpb>>>(img, rand_t, false_t, lscale, out);
    cl_lse_kernel<<<64, tpb>>>(out);
}